// round 15
// baseline (speedup 1.0000x reference)
#include <cuda_runtime.h>
#include <cuda_fp16.h>
#include <cstdint>
#include <cstddef>

// ---------------------------------------------------------------------------
// Problem constants
// ---------------------------------------------------------------------------
static constexpr int D_DIM  = 2496;   // 16*13*12
static constexpr int B_ROWS = 4096;
static constexpr int S_ROWS = 2048;

// Centered formulation: x~ = x - 0.5, m~ = m - 0.5 (sq_dist shift-invariant).
// out = -0.002*|x~|^2 - 0.002*|m~|^2 + 0.004*(x~.m~)
static constexpr float K_CROSS = 0.004f;
static constexpr float K_SQ    = -0.002f;

// GEMM tiling: quarter tiles, fp16 f16-acc mma, BK=64 stages, 3-stage ring.
// (R11 config — pinned at the legacy-mma dispatch wall; do not touch.)
static constexpr int BM = 64;
static constexpr int BN = 128;
static constexpr int BK = 64;
static constexpr int KITERS = D_DIM / BK; // 39 exact
static constexpr int STAGES = 3;
static constexpr int NTHREADS = 256;      // 8 warps: 2(M) x 4(N), warp tile 32x32

// Padded smem rows: 128 B data + 16 B pad = 144 B stride (conflict-free).
static constexpr int ROW_STRIDE  = 144;
static constexpr int A_ST_BYTES  = BM * ROW_STRIDE;           // 9216
static constexpr int B_ST_BYTES  = BN * ROW_STRIDE;           // 18432
static constexpr int STAGE_BYTES = A_ST_BYTES + B_ST_BYTES;   // 27648
static constexpr int OFF_STATS   = STAGES * STAGE_BYTES;      // 82944
static constexpr int SMEM_BYTES  = OFF_STATS + (BM + BN) * 4; // 83712

// ---------------------------------------------------------------------------
// Device scratch
// ---------------------------------------------------------------------------
__device__ __align__(128) __half g_Xh[(size_t)B_ROWS * D_DIM];
__device__ __align__(128) __half g_Mh[(size_t)S_ROWS * D_DIM];
__device__ float g_ax[B_ROWS];   // -0.002 * |x~|^2
__device__ float g_bx[S_ROWS];   // -0.002 * |m~|^2

// ---------------------------------------------------------------------------
// Helpers
// ---------------------------------------------------------------------------
__device__ __forceinline__ uint32_t smem_u32(const void* p) {
    uint32_t a;
    asm("{ .reg .u64 t; cvta.to.shared.u64 t, %1; cvt.u32.u64 %0, t; }"
        : "=r"(a) : "l"(p));
    return a;
}

__device__ __forceinline__ void cp_async16(uint32_t dst, const void* src) {
    asm volatile("cp.async.cg.shared.global [%0], [%1], 16;" :: "r"(dst), "l"(src));
}

__device__ __forceinline__ void ldmat_x4(uint32_t* r, uint32_t addr) {
    asm volatile("ldmatrix.sync.aligned.m8n8.x4.shared.b16 {%0,%1,%2,%3}, [%4];"
                 : "=r"(r[0]), "=r"(r[1]), "=r"(r[2]), "=r"(r[3]) : "r"(addr));
}

__device__ __forceinline__ void mma_f16acc(uint32_t* c, const uint32_t* a,
                                           const uint32_t* b) {
    asm volatile(
        "mma.sync.aligned.m16n8k16.row.col.f16.f16.f16.f16 "
        "{%0,%1}, {%2,%3,%4,%5}, {%6,%7}, {%0,%1};"
        : "+r"(c[0]), "+r"(c[1])
        : "r"(a[0]), "r"(a[1]), "r"(a[2]), "r"(a[3]), "r"(b[0]), "r"(b[1]));
}

// ---------------------------------------------------------------------------
// Stage loader: A tile 64x64 fp16, B tile 128x64 fp16 via cp.async (16B)
// ---------------------------------------------------------------------------
__device__ __forceinline__ void load_stage(uint32_t sbase,
                                           const __half* __restrict__ Xt,
                                           const __half* __restrict__ Mt,
                                           int tid) {
#pragma unroll
    for (int i = 0; i < 2; i++) {                 // A: 512 chunks
        int idx = i * NTHREADS + tid;
        int row = idx >> 3, ch = idx & 7;
        cp_async16(sbase + row * ROW_STRIDE + ch * 16,
                   Xt + (size_t)row * D_DIM + ch * 8);
    }
#pragma unroll
    for (int i = 0; i < 4; i++) {                 // B: 1024 chunks
        int idx = i * NTHREADS + tid;
        int row = idx >> 3, ch = idx & 7;
        cp_async16(sbase + A_ST_BYTES + row * ROW_STRIDE + ch * 16,
                   Mt + (size_t)row * D_DIM + ch * 8);
    }
}

// ---------------------------------------------------------------------------
// Convert: one WARP per row; lane handles 2 consecutive float4 (32 B
// streaming read via __ldcs, one 16 B store). PDL trigger at block end.
// ---------------------------------------------------------------------------
static constexpr int ROW_F4 = D_DIM / 4;        // 624 float4 per row
static constexpr int ROWS_PER_BLK = 8;

__global__ void __launch_bounds__(256)
convert_all_kernel(const float* __restrict__ X, const float* __restrict__ M) {
    const int wid  = threadIdx.x >> 5;
    const int lane = threadIdx.x & 31;
    const int b    = blockIdx.x * ROWS_PER_BLK + wid;
    const bool isX = (b < B_ROWS);
    const int row  = isX ? b : b - B_ROWS;
    const float4* src = (const float4*)((isX ? X : M) + (size_t)row * D_DIM);
    uint4* dst = (uint4*)((isX ? g_Xh : g_Mh) + (size_t)row * D_DIM);
    float* coef = isX ? &g_ax[row] : &g_bx[row];

    float acc = 0.f;
#pragma unroll 3
    for (int i = lane * 2; i < ROW_F4; i += 64) {
        float4 v0 = __ldcs(src + i);
        float4 v1 = __ldcs(src + i + 1);
        float c0 = v0.x - 0.5f, c1 = v0.y - 0.5f;
        float c2 = v0.z - 0.5f, c3 = v0.w - 0.5f;
        float c4 = v1.x - 0.5f, c5 = v1.y - 0.5f;
        float c6 = v1.z - 0.5f, c7 = v1.w - 0.5f;
        acc = fmaf(c0, c0, acc);
        acc = fmaf(c1, c1, acc);
        acc = fmaf(c2, c2, acc);
        acc = fmaf(c3, c3, acc);
        acc = fmaf(c4, c4, acc);
        acc = fmaf(c5, c5, acc);
        acc = fmaf(c6, c6, acc);
        acc = fmaf(c7, c7, acc);
        __half2 h0 = __floats2half2_rn(c0, c1);
        __half2 h1 = __floats2half2_rn(c2, c3);
        __half2 h2 = __floats2half2_rn(c4, c5);
        __half2 h3 = __floats2half2_rn(c6, c7);
        uint4 o;
        o.x = *(uint32_t*)&h0;
        o.y = *(uint32_t*)&h1;
        o.z = *(uint32_t*)&h2;
        o.w = *(uint32_t*)&h3;
        dst[i >> 1] = o;
    }
#pragma unroll
    for (int o = 16; o > 0; o >>= 1) acc += __shfl_xor_sync(0xffffffffu, acc, o);
    if (lane == 0) *coef = acc * K_SQ;

    // PDL: all writes of this block are done — let the dependent grid launch.
    asm volatile("griddepcontrol.launch_dependents;" ::: "memory");
}

// ---------------------------------------------------------------------------
// GEMM + fused epilogue: out[b,s] = ax[b] + bx[s] + 0.004 * cross
// 256 threads = 8 warps in 2(M) x 4(N); warp tile 32x32. 2 CTAs/SM.
// Launched with programmatic stream serialization; waits on the convert
// grid before its first dependent global read.
// ---------------------------------------------------------------------------
__global__ void __launch_bounds__(NTHREADS, 2)
gemm_kernel(float* __restrict__ out) {
    extern __shared__ char smem[];
    const uint32_t smem_base = smem_u32(smem);
    const int tid    = threadIdx.x;
    const int wid    = tid >> 5;
    const int lane   = tid & 31;
    const int warp_m = wid >> 2;          // 0..1
    const int warp_n = wid & 3;           // 0..3
    const int bn     = blockIdx.x;        // 0..15
    const int bm     = blockIdx.y;        // 0..63

    const __half* Xbase = g_Xh + (size_t)(bm * BM) * D_DIM;
    const __half* Mbase = g_Mh + (size_t)(bn * BN) * D_DIM;
    float* xs_s = (float*)(smem + OFF_STATS);
    float* ms_s = xs_s + BM;

    // PDL: block until the convert grid's writes are visible.
    asm volatile("griddepcontrol.wait;" ::: "memory");

    if (tid < BM) xs_s[tid] = g_ax[bm * BM + tid];
    if (tid < BN) ms_s[tid] = g_bx[bn * BN + tid];

#pragma unroll
    for (int s = 0; s < STAGES - 1; s++) {
        load_stage(smem_base + s * STAGE_BYTES,
                   Xbase + (size_t)s * BK, Mbase + (size_t)s * BK, tid);
        asm volatile("cp.async.commit_group;" ::: "memory");
    }

    uint32_t acc[2][4][2];
#pragma unroll
    for (int t = 0; t < 2; t++)
#pragma unroll
        for (int u = 0; u < 4; u++) { acc[t][u][0] = 0u; acc[t][u][1] = 0u; }

    const int a_row = warp_m * 32 + (lane & 15);
    const int a_sel = (lane >> 4) * 16;
    const int b_grp = lane >> 3;
    const int b_row = warp_n * 32 + ((b_grp >> 1) * 8) + (lane & 7);
    const int b_sel = (b_grp & 1) * 16;

    int slot_cur = 0;
    int slot_pre = 2;

#pragma unroll 1
    for (int kk = 0; kk < KITERS; kk++) {
        asm volatile("cp.async.wait_group 1;" ::: "memory");
        __syncthreads();

        int kn = kk + STAGES - 1;
        if (kn < KITERS) {
            load_stage(smem_base + slot_pre * STAGE_BYTES,
                       Xbase + (size_t)kn * BK, Mbase + (size_t)kn * BK, tid);
        }
        asm volatile("cp.async.commit_group;" ::: "memory");

        const uint32_t sA = smem_base + slot_cur * STAGE_BYTES;
        const uint32_t sB = sA + A_ST_BYTES;
        slot_cur = (slot_cur == 2) ? 0 : slot_cur + 1;
        slot_pre = (slot_pre == 2) ? 0 : slot_pre + 1;

#pragma unroll
        for (int ks = 0; ks < 4; ks++) {              // four k16 steps per BK=64
            const int koff = ks * 32;
            uint32_t a[2][4], b[4][2];
#pragma unroll
            for (int t = 0; t < 2; t++)
                ldmat_x4(a[t], sA + (a_row + t * 16) * ROW_STRIDE + koff + a_sel);
#pragma unroll
            for (int v = 0; v < 2; v++) {
                uint32_t r[4];
                ldmat_x4(r, sB + (b_row + v * 16) * ROW_STRIDE + koff + b_sel);
                b[v * 2 + 0][0] = r[0]; b[v * 2 + 0][1] = r[1];
                b[v * 2 + 1][0] = r[2]; b[v * 2 + 1][1] = r[3];
            }
#pragma unroll
            for (int t = 0; t < 2; t++)
#pragma unroll
                for (int u = 0; u < 4; u++)
                    mma_f16acc(acc[t][u], a[t], b[u]);
        }
    }

    // ---------------- Epilogue ----------------
    const int g  = lane >> 2;
    const int tg = lane & 3;

#pragma unroll
    for (int t = 0; t < 2; t++) {
        const int r0 = warp_m * 32 + t * 16 + g;
        const float axa = xs_s[r0];
        const float axb = xs_s[r0 + 8];
        float* o0 = out + (size_t)(bm * BM + r0) * S_ROWS + bn * BN;
        float* o1 = o0 + (size_t)8 * S_ROWS;
#pragma unroll
        for (int u = 0; u < 4; u++) {
            const int col = warp_n * 32 + u * 8 + tg * 2;
            const float m0 = ms_s[col], m1 = ms_s[col + 1];
            float2 clo = __half22float2(*(__half2*)&acc[t][u][0]);
            float2 chi = __half22float2(*(__half2*)&acc[t][u][1]);
            float2 v0, v1;
            v0.x = axa + m0 + K_CROSS * clo.x;
            v0.y = axa + m1 + K_CROSS * clo.y;
            v1.x = axb + m0 + K_CROSS * chi.x;
            v1.y = axb + m1 + K_CROSS * chi.y;
            *(float2*)(o0 + col) = v0;
            *(float2*)(o1 + col) = v1;
        }
    }
}

// ---------------------------------------------------------------------------
// Launch: single stream, GEMM launched with programmatic dependent launch so
// its CTAs are resident while the convert grid drains.
// ---------------------------------------------------------------------------
extern "C" void kernel_launch(void* const* d_in, const int* in_sizes, int n_in,
                              void* d_out, int out_size) {
    (void)n_in; (void)out_size;
    const float* X = (const float*)d_in[0];   // observation        [4096, 2496]
    const float* M = (const float*)d_in[1];   // observation_matrix [2048, 2496]
    if (in_sizes[0] == S_ROWS * D_DIM) {      // robust to ordering
        X = (const float*)d_in[1];
        M = (const float*)d_in[0];
    }
    float* out = (float*)d_out;

    cudaFuncSetAttribute(gemm_kernel,
                         cudaFuncAttributeMaxDynamicSharedMemorySize, SMEM_BYTES);

    convert_all_kernel<<<(B_ROWS + S_ROWS) / ROWS_PER_BLK, 256>>>(X, M);

    cudaLaunchConfig_t cfg = {};
    cfg.gridDim  = dim3(S_ROWS / BN, B_ROWS / BM);   // (16, 64) = 1024 CTAs
    cfg.blockDim = dim3(NTHREADS, 1, 1);
    cfg.dynamicSmemBytes = SMEM_BYTES;
    cfg.stream = 0;
    cudaLaunchAttribute attr[1];
    attr[0].id = cudaLaunchAttributeProgrammaticStreamSerialization;
    attr[0].val.programmaticStreamSerializationAllowed = 1;
    cfg.attrs = attr;
    cfg.numAttrs = 1;
    cudaLaunchKernelEx(&cfg, gemm_kernel, out);
}